// round 14
// baseline (speedup 1.0000x reference)
#include <cuda_runtime.h>
#include <cstdint>
#include <cstring>

#define NB 256   // batch
#define NPTS 256 // points per side (N == M)
#define ND 4
#define RSTRIDE 257  // padded row stride for reduction buffers (bank-conflict-free)

// per-batch results: [0..NB): eucl_non_zero, [NB..2NB): eucl_zero
__device__ float g_part[2 * NB];
__device__ int   g_count = 0;

static __device__ __forceinline__ uint64_t dup2(float v) {
    uint64_t r; asm("mov.b64 %0, {%1, %1};" : "=l"(r) : "f"(v)); return r;
}
static __device__ __forceinline__ uint64_t ffma2(uint64_t a, uint64_t b, uint64_t c) {
    uint64_t d; asm("fma.rn.f32x2 %0, %1, %2, %3;" : "=l"(d) : "l"(a), "l"(b), "l"(c)); return d;
}
static __device__ __forceinline__ uint64_t add2(uint64_t a, uint64_t b) {
    uint64_t d; asm("add.rn.f32x2 %0, %1, %2;" : "=l"(d) : "l"(a), "l"(b)); return d;
}
static __device__ __forceinline__ float2 asf2(uint64_t v) {
    float2 f; memcpy(&f, &v, 8); return f;   // register-pair aliasing, no SASS op
}

__global__ __launch_bounds__(256) void chamfer_kernel(
    const float* __restrict__ target,
    const float* __restrict__ reco,
    const int*   __restrict__ in_pid,
    const int*   __restrict__ out_pid,
    float*       __restrict__ out)
{
    // reco tile, pair-interleaved for f32x2 (pair p = cols 2p, 2p+1):
    //  cA[p] = { (-2x0,-2x1), (-2y0,-2y1) }, cB = comps 2,3
    //  cC[p] = ( n2y0+pen0 , n2y1+pen1 )
    __shared__ ulonglong2 cA[NPTS/2], cB[NPTS/2];
    __shared__ uint64_t   cC[NPTS/2];
    __shared__ float4     rowsm[NPTS];   // target rows (plain)
    __shared__ float      rowc[NPTS];    // n2x + penx
    __shared__ int        rmasks[NPTS];  // mask_x
    __shared__ int        cmasks[NPTS];  // mask_y
    __shared__ float      rowred[16 * RSTRIDE];  // row-min partials over tj
    __shared__ float      colred[16 * RSTRIDE];  // col-min partials over ti
    __shared__ float4     swred[8];
    __shared__ int        s_last;

    const int b  = blockIdx.x;
    const int t  = threadIdx.x;
    const int ti = t >> 4;     // row group: rows [ti*16, ti*16+16)
    const int tj = t & 15;     // col group: cols [tj*16, tj*16+16) = pairs [tj*8, tj*8+8)

    const float4* tg4 = (const float4*)(target + (size_t)b * NPTS * ND);
    const float4* rc4 = (const float4*)(reco   + (size_t)b * NPTS * ND);
    const int*    ip  = in_pid  + b * NPTS;
    const int*    op  = out_pid + b * NPTS;

    // ---- prologue: each thread loads 1 target pt + 1 reco pt ----
    float4 tv = tg4[t];
    float4 rv = rc4[t];
    int    tp = ip[t];
    int    rp = op[t];

    const float n2x = tv.x*tv.x + tv.y*tv.y + tv.z*tv.z + tv.w*tv.w;
    const float n2y = rv.x*rv.x + rv.y*rv.y + rv.z*rv.z + rv.w*rv.w;

    {
        int pair = t >> 1, lane = t & 1;
        ((float*)cA)[pair*4 + lane]     = -2.0f * rv.x;
        ((float*)cA)[pair*4 + 2 + lane] = -2.0f * rv.y;
        ((float*)cB)[pair*4 + lane]     = -2.0f * rv.z;
        ((float*)cB)[pair*4 + 2 + lane] = -2.0f * rv.w;
        ((float*)cC)[t] = n2y + (rp != 0 ? 0.0f : 1e20f);
        rowsm[t]  = tv;
        rowc[t]   = n2x + (tp != 0 ? 0.0f : 1e20f);
        rmasks[t] = (tp != 0);
        cmasks[t] = (rp != 0);
    }

    // per-thread norm contributions for edge cases
    float c_nrmx  = (tp != 0) ? sqrtf(n2x) : 0.0f;  // sum ||x|| over mask_x
    float c_nrmy0 = (rp != 0) ? 0.0f : sqrtf(n2y);  // sum ||y|| over ~mask_y

    const int nx = __syncthreads_count(tp != 0);
    const int ny = __syncthreads_count(rp != 0);
    // (counts also act as the barrier making shared tiles visible)

    // ---- cache this thread's 8 col-pairs in registers ----
    ulonglong2 A[8], Bv[8];
    uint64_t   C[8];
    #pragma unroll
    for (int k = 0; k < 8; ++k) {
        A[k]  = cA[tj*8 + k];
        Bv[k] = cB[tj*8 + k];
        C[k]  = cC[tj*8 + k];
    }

    float colLo[8], colHi[8];
    #pragma unroll
    for (int k = 0; k < 8; ++k) { colLo[k] = 3.0e38f; colHi[k] = 3.0e38f; }

    // ---- main loop: 16 rows x 8 col-pairs; each d2 feeds BOTH min directions ----
    #pragma unroll 4
    for (int r16 = 0; r16 < 16; ++r16) {
        const int row = ti * 16 + r16;
        float4 x = rowsm[row];                    // broadcast within half... conflict-free
        const uint64_t rxx = dup2(x.x), rxy = dup2(x.y);
        const uint64_t rxz = dup2(x.z), rxw = dup2(x.w);
        const uint64_t rc2 = dup2(rowc[row]);     // n2x + penx
        float racc = 3.0e38f;
        #pragma unroll
        for (int k = 0; k < 8; ++k) {
            uint64_t s = ffma2(A[k].x, rxx, C[k]);
            s = ffma2(A[k].y, rxy, s);
            s = ffma2(Bv[k].x, rxz, s);
            s = ffma2(Bv[k].y, rxw, s);
            s = add2(s, rc2);                     // full d^2 + both pens (packed)
            float2 f = asf2(s);
            racc = fminf(racc, fminf(f.x, f.y));
            colLo[k] = fminf(colLo[k], f.x);
            colHi[k] = fminf(colHi[k], f.y);
        }
        rowred[tj * RSTRIDE + row] = racc;        // padded: conflict-free STS
    }

    // ---- store col partials ----
    #pragma unroll
    for (int k = 0; k < 8; ++k) {
        colred[ti * RSTRIDE + tj*16 + 2*k]     = colLo[k];
        colred[ti * RSTRIDE + tj*16 + 2*k + 1] = colHi[k];
    }
    __syncthreads();

    // ---- final row/col mins: thread t owns row t and col t ----
    float rmin = rowred[t];
    float cmin = colred[t];
    #pragma unroll
    for (int w = 1; w < 16; ++w) {
        rmin = fminf(rmin, rowred[w * RSTRIDE + t]);
        cmin = fminf(cmin, colred[w * RSTRIDE + t]);
    }
    // clamp cancellation negatives; sqrt; mask
    float sum_x = rmasks[t] ? sqrtf(fmaxf(rmin, 0.0f)) : 0.0f;  // min_xy contribution
    float sum_y = cmasks[t] ? sqrtf(fmaxf(cmin, 0.0f)) : 0.0f;  // min_yx contribution

    // ---- warp shfl reduce of 4 sums ----
    #pragma unroll
    for (int off = 16; off > 0; off >>= 1) {
        sum_x   += __shfl_xor_sync(0xffffffffu, sum_x, off);
        sum_y   += __shfl_xor_sync(0xffffffffu, sum_y, off);
        c_nrmx  += __shfl_xor_sync(0xffffffffu, c_nrmx, off);
        c_nrmy0 += __shfl_xor_sync(0xffffffffu, c_nrmy0, off);
    }
    const int wid = t >> 5, lane = t & 31;
    if (lane == 0) swred[wid] = make_float4(sum_x, sum_y, c_nrmx, c_nrmy0);
    __syncthreads();

    // ---- thread 0: per-batch outputs ----
    if (t == 0) {
        float sum_xy = 0.0f, sum_yx = 0.0f, sum_nrmx = 0.0f, sum_nrmy0 = 0.0f;
        #pragma unroll
        for (int w = 0; w < 8; ++w) {
            float4 r = swred[w];
            sum_xy += r.x; sum_yx += r.y; sum_nrmx += r.z; sum_nrmy0 += r.w;
        }
        float n_in  = (float)max(1, nx);
        float n_out = (float)max(1, ny);
        float normal = 0.5f * (sum_xy / n_out + sum_yx / n_in);
        float e_nz = (ny == 0) ? (sum_nrmx / n_in)
                   : ((nx == 0) ? 0.0f : normal);
        float e_z  = sum_nrmy0 / (float)max(1, NPTS - ny);
        g_part[b]      = e_nz;
        g_part[NB + b] = e_z;
        __threadfence();
        int old = atomicAdd(&g_count, 1);
        s_last = (old == NB - 1);
    }
    __syncthreads();

    // ---- last block: mean over batches (1 batch per thread) ----
    if (s_last) {
        if (t == 0) { g_count = 0; __threadfence(); }
        float e0 = __ldcg(&g_part[t]);
        float e1 = __ldcg(&g_part[NB + t]);
        #pragma unroll
        for (int off = 16; off > 0; off >>= 1) {
            e0 += __shfl_xor_sync(0xffffffffu, e0, off);
            e1 += __shfl_xor_sync(0xffffffffu, e1, off);
        }
        if (lane == 0) swred[wid] = make_float4(e0, e1, 0.0f, 0.0f);
        __syncthreads();
        if (t == 0) {
            float a = 0.0f, b2 = 0.0f;
            #pragma unroll
            for (int w = 0; w < 8; ++w) { a += swred[w].x; b2 += swred[w].y; }
            out[0] = a * (1.0f / NB);
            out[1] = b2 * (1.0f / NB);
        }
    }
}

extern "C" void kernel_launch(void* const* d_in, const int* in_sizes, int n_in,
                              void* d_out, int out_size)
{
    const float* target  = (const float*)d_in[0];
    const float* reco    = (const float*)d_in[1];
    const int*   in_pid  = (const int*)d_in[2];
    const int*   out_pid = (const int*)d_in[3];
    float* out = (float*)d_out;

    chamfer_kernel<<<NB, 256>>>(target, reco, in_pid, out_pid, out);
}